// round 16
// baseline (speedup 1.0000x reference)
#include <cuda_runtime.h>

#define KSZ   2
#define CIN   3
#define COUT  16
#define HIN   256
#define WIN   256
#define HF    255
#define WF    255
#define HO    254
#define WO    254
#define BATCH 64
#define NPIX  (BATCH * HF * WF)
#define BN_EPS 1e-5f

#define NTAP  12
#define NTRI  78
#define NSTAT (NTAP + NTRI)
#define CSTR  14            // per-channel: 12 scaled weights + shift + pad (112B, 16B-aligned)
#define SROWS 32            // feat rows per strip; stats block = 2 strips
#define TPBASE 124          // thin region: pair-columns 124..127 (feat cols 248..255)

typedef unsigned long long u64;

__device__ __forceinline__ u64 pk2(float lo, float hi) {
    u64 r; asm("mov.b64 %0,{%1,%2};" : "=l"(r) : "f"(lo), "f"(hi)); return r;
}
__device__ __forceinline__ void up2(u64 v, float& lo, float& hi) {
    asm("mov.b64 {%0,%1},%2;" : "=f"(lo), "=f"(hi) : "l"(v));
}
__device__ __forceinline__ u64 fma2(u64 a, u64 b, u64 c) {
    u64 d; asm("fma.rn.f32x2 %0,%1,%2,%3;" : "=l"(d) : "l"(a), "l"(b), "l"(c)); return d;
}
__device__ __forceinline__ u64 mul2(u64 a, u64 b) {
    u64 d; asm("mul.rn.f32x2 %0,%1,%2;" : "=l"(d) : "l"(a), "l"(b)); return d;
}
__device__ __forceinline__ u64 add2(u64 a, u64 b) {
    u64 d; asm("add.rn.f32x2 %0,%1,%2;" : "=l"(d) : "l"(a), "l"(b)); return d;
}
__device__ __forceinline__ float tha(float x) {
    float y; asm("tanh.approx.f32 %0,%1;" : "=f"(y) : "f"(x)); return y;
}

// ---------------- constant: per-channel [12 w*scale, shift, pad] (128-bit loads) ----------------
__constant__ __align__(16) u64 c_all[COUT * CSTR];

// ---------------- device scratch (zero-initialized at module load) ----------------
__device__ double g_stat[NSTAT];
__device__ __align__(16) u64 g_all[COUT * CSTR];

// 16-channel conv+BN+relu+tanh core; weights via ULDC.128, packed f32x2 acc
__device__ __forceinline__ void conv_core(const u64 e[CIN][3], const u64 o[CIN][3],
                                          u64 acc[2]) {
#pragma unroll 1
    for (int c = 0; c < COUT; c++) {
        const ulonglong2* wv = reinterpret_cast<const ulonglong2*>(c_all + c * CSTR);
        const ulonglong2 p0 = wv[0], p1 = wv[1], p2 = wv[2];
        const ulonglong2 p3 = wv[3], p4 = wv[4], p5 = wv[5], p6 = wv[6];
        const u64 sh = p6.x;
#pragma unroll
        for (int i = 0; i < 2; i++) {
            u64 v0 = fma2(p0.x, e[0][i], sh);     // shift folded into chain init
            v0 = fma2(p0.y, o[0][i],     v0);
            v0 = fma2(p1.x, e[0][i + 1], v0);
            v0 = fma2(p1.y, o[0][i + 1], v0);
            v0 = fma2(p2.x, e[1][i],     v0);
            v0 = fma2(p2.y, o[1][i],     v0);
            u64 v1 = mul2(p3.x, e[1][i + 1]);
            v1 = fma2(p3.y, o[1][i + 1], v1);
            v1 = fma2(p4.x, e[2][i],     v1);
            v1 = fma2(p4.y, o[2][i],     v1);
            v1 = fma2(p5.x, e[2][i + 1], v1);
            v1 = fma2(p5.y, o[2][i + 1], v1);
            u64 v = add2(v0, v1);
            float lo, hi; up2(v, lo, hi);
            float ta = tha(fmaxf(lo, 0.f));
            float tb = tha(fmaxf(hi, 0.f));
            acc[i] = add2(acc[i], pk2(ta, tb));   // packed accumulate (1 fma-op)
        }
    }
}

// ---------------------------------------------------------------------------
// Kernel 1: tap sums + Gram matrix (R15 verbatim — proven 34us).
// ---------------------------------------------------------------------------
__global__ void __launch_bounds__(256, 2) stats_kernel(const float* __restrict__ x) {
    float S[NTAP];
    float G[NTRI];
#pragma unroll
    for (int k = 0; k < NTAP; k++) S[k] = 0.f;
#pragma unroll
    for (int k = 0; k < NTRI; k++) G[k] = 0.f;

    const int p  = threadIdx.x & 127;
    const int s  = threadIdx.x >> 7;
    const int j  = 2 * p;
    const int i0 = blockIdx.x * (2 * SROWS) + s * SROWS;
    const int nr = (i0 + SROWS <= HF) ? SROWS : (HF - i0);
    const bool has2 = (j + 1 < WF);
    const float* xb = x + (size_t)blockIdx.y * CIN * HIN * WIN;

    {
        const float* p0 = xb + (size_t)i0 * WIN + j;
        float t[CIN][3], bt[CIN][3], n[CIN][3];
#pragma unroll
        for (int ci = 0; ci < CIN; ci++) {
            const float* q = p0 + (size_t)ci * HIN * WIN;
            float2 a = *(const float2*)q;
            float2 b = *(const float2*)(q + WIN);
            t[ci][0] = a.x;  t[ci][1] = a.y;
            t[ci][2] = has2 ? __ldg(q + 2) : 0.f;
            bt[ci][0] = b.x; bt[ci][1] = b.y;
            bt[ci][2] = has2 ? __ldg(q + WIN + 2) : 0.f;
        }
        for (int r = 0; r < nr; r++) {
            const int pr = (i0 + r + 2 < HIN) ? (r + 2) : (HIN - 1 - i0);
            const float* pn = p0 + (size_t)pr * WIN;
#pragma unroll
            for (int ci = 0; ci < CIN; ci++) {
                const float* q = pn + (size_t)ci * HIN * WIN;
                float2 a = *(const float2*)q;
                n[ci][0] = a.x; n[ci][1] = a.y;
                n[ci][2] = has2 ? __ldg(q + 2) : 0.f;
            }

            float xv[NTAP];
#pragma unroll
            for (int ci = 0; ci < CIN; ci++) {
                xv[ci * 4 + 0] = t[ci][0];
                xv[ci * 4 + 1] = t[ci][1];
                xv[ci * 4 + 2] = bt[ci][0];
                xv[ci * 4 + 3] = bt[ci][1];
            }
#pragma unroll
            for (int k = 0; k < NTAP; k++) {
                S[k] += xv[k];
#pragma unroll
                for (int l = 0; l <= k; l++)
                    G[k * (k + 1) / 2 + l] = fmaf(xv[k], xv[l], G[k * (k + 1) / 2 + l]);
            }

            if (has2) {
                float yv[NTAP];
#pragma unroll
                for (int ci = 0; ci < CIN; ci++) {
                    yv[ci * 4 + 0] = t[ci][1];
                    yv[ci * 4 + 1] = t[ci][2];
                    yv[ci * 4 + 2] = bt[ci][1];
                    yv[ci * 4 + 3] = bt[ci][2];
                }
#pragma unroll
                for (int k = 0; k < NTAP; k++) {
                    S[k] += yv[k];
#pragma unroll
                    for (int l = 0; l <= k; l++)
                        G[k * (k + 1) / 2 + l] = fmaf(yv[k], yv[l], G[k * (k + 1) / 2 + l]);
                }
            }

#pragma unroll
            for (int ci = 0; ci < CIN; ci++) {
                t[ci][0] = bt[ci][0]; t[ci][1] = bt[ci][1]; t[ci][2] = bt[ci][2];
                bt[ci][0] = n[ci][0]; bt[ci][1] = n[ci][1]; bt[ci][2] = n[ci][2];
            }
        }
    }

    const unsigned m = 0xffffffffu;
#pragma unroll
    for (int k = 0; k < NTAP; k++) {
        float a = S[k];
#pragma unroll
        for (int o = 16; o > 0; o >>= 1) a += __shfl_xor_sync(m, a, o);
        S[k] = a;
    }
#pragma unroll
    for (int k = 0; k < NTRI; k++) {
        float a = G[k];
#pragma unroll
        for (int o = 16; o > 0; o >>= 1) a += __shfl_xor_sync(m, a, o);
        G[k] = a;
    }

    __shared__ float red[8][NSTAT];
    const int warp = threadIdx.x >> 5, lane = threadIdx.x & 31;
    if (lane == 0) {
#pragma unroll
        for (int k = 0; k < NTAP; k++) red[warp][k] = S[k];
#pragma unroll
        for (int k = 0; k < NTRI; k++) red[warp][NTAP + k] = G[k];
    }
    __syncthreads();
    if (threadIdx.x < NSTAT) {
        float tot = 0.f;
#pragma unroll
        for (int w = 0; w < 8; w++) tot += red[w][threadIdx.x];
        atomicAdd(&g_stat[threadIdx.x], (double)tot);
    }
}

// ---------------------------------------------------------------------------
// Kernel 2: stage stats -> smem, re-zero g_stat, reconstruct per-channel
// stats, fold BN (conv bias cancels under train-mode BN).
// ---------------------------------------------------------------------------
__global__ void finalize_kernel(const float* __restrict__ w,
                                const float* __restrict__ gamma,
                                const float* __restrict__ beta) {
    __shared__ double st[NSTAT];
    const int t = threadIdx.x;
    if (t < NSTAT) st[t] = g_stat[t];
    __syncthreads();
    if (t < NSTAT) g_stat[t] = 0.0;

    if (t >= COUT) return;
    const int c = t;
    const double N = (double)NPIX;
    double wc[NTAP];
#pragma unroll
    for (int k = 0; k < NTAP; k++) wc[k] = (double)w[c * NTAP + k];

    double mean = 0.0;
#pragma unroll
    for (int k = 0; k < NTAP; k++) mean += wc[k] * st[k];
    mean /= N;

    double e2 = 0.0;
#pragma unroll
    for (int k = 0; k < NTAP; k++) {
#pragma unroll
        for (int l = 0; l <= k; l++) {
            double g = st[NTAP + k * (k + 1) / 2 + l];
            double tt = wc[k] * wc[l] * g;
            e2 += (l == k) ? tt : 2.0 * tt;
        }
    }
    e2 /= N;
    double var = e2 - mean * mean;
    float scale = gamma[c] * rsqrtf((float)var + BN_EPS);
    float shift = beta[c] - (float)mean * scale;
#pragma unroll
    for (int k = 0; k < NTAP; k++) {
        float ws = w[c * NTAP + k] * scale;
        g_all[c * CSTR + k] = pk2(ws, ws);
    }
    g_all[c * CSTR + NTAP]     = pk2(shift, shift);
    g_all[c * CSTR + NTAP + 1] = 0ull;           // pad (keeps replays deterministic)
}

// ---------------------------------------------------------------------------
// Kernel 3: fused conv+BN+relu+tanh+window (R13 tiling — proven).
// ---------------------------------------------------------------------------
__global__ void __launch_bounds__(256, 4) fused_out_kernel(const float* __restrict__ x,
                                                           float* __restrict__ out) {
    __shared__ union {
        struct { u64 pe[CIN][17][33]; u64 st[16][33]; } m;   // main tile
        struct { u64 pe[CIN][129][5]; u64 st[128][4]; } t;   // thin tile
    } sm;

    const int tid = threadIdx.x;
    const int b   = blockIdx.z;
    const float* xb = x + (size_t)b * CIN * HIN * WIN;
    const float inv = 1.0f / (COUT * KSZ * KSZ);

    if (blockIdx.y < 17) {
        const int oy0 = blockIdx.y * 15;
        const int ox0 = blockIdx.x * 62;

        for (int idx = tid; idx < CIN * 17 * 33; idx += 256) {
            const int jc = idx % 33;
            const int t2 = idx / 33;
            const int r  = t2 % 17;
            const int ci = t2 / 17;
            const int gr = oy0 + r, gc = ox0 + 2 * jc;
            u64 v = 0ull;
            if (gr < HIN && gc < WIN)
                v = *(const u64*)&xb[(size_t)(ci * HIN + gr) * WIN + gc];
            sm.m.pe[ci][r][jc] = v;
        }
        __syncthreads();

        const int jp = tid & 31;
        const int r0 = (tid >> 5) * 2;

        u64 e[CIN][3], o[CIN][3];
#pragma unroll
        for (int ci = 0; ci < CIN; ci++) {
#pragma unroll
            for (int i = 0; i < 3; i++) {
                u64 ev = sm.m.pe[ci][r0 + i][jp];
                u64 en = sm.m.pe[ci][r0 + i][jp + 1];
                float elo, ehi, nlo, nhi;
                up2(ev, elo, ehi); up2(en, nlo, nhi);
                e[ci][i] = ev;
                o[ci][i] = pk2(ehi, nlo);
            }
        }

        u64 acc[2] = {0ull, 0ull};
        conv_core(e, o, acc);
        sm.m.st[r0 + 0][jp] = acc[0];
        sm.m.st[r0 + 1][jp] = acc[1];
        __syncthreads();

        const float* stf = (const float*)sm.m.st;
        for (int p = tid; p < 62 * 15; p += 256) {
            const int oy = p / 62, ox_ = p - oy * 62;
            const int oi = oy0 + oy, oj = ox0 + ox_;
            if (oi < HO) {
                const float* rp = stf + oy * 66 + ox_;
                out[(size_t)(b * HO + oi) * WO + oj] =
                    (rp[0] + rp[1] + rp[66] + rp[67]) * inv;
            }
        }
    } else {
        if (blockIdx.x != 0) return;
        const int oy0 = (blockIdx.y == 17) ? 0 : 127;

        for (int idx = tid; idx < CIN * 129 * 5; idx += 256) {
            const int jc = idx % 5;
            const int t2 = idx / 5;
            const int r  = t2 % 129;
            const int ci = t2 / 129;
            const int gr = oy0 + r, gc = 2 * (TPBASE + jc);
            u64 v = 0ull;
            if (gr < HIN && gc < WIN)
                v = *(const u64*)&xb[(size_t)(ci * HIN + gr) * WIN + gc];
            sm.t.pe[ci][r][jc] = v;
        }
        __syncthreads();

        const int jp = tid & 3;
        const int r0 = (tid >> 2) * 2;

        u64 e[CIN][3], o[CIN][3];
#pragma unroll
        for (int ci = 0; ci < CIN; ci++) {
#pragma unroll
            for (int i = 0; i < 3; i++) {
                u64 ev = sm.t.pe[ci][r0 + i][jp];
                u64 en = sm.t.pe[ci][r0 + i][jp + 1];
                float elo, ehi, nlo, nhi;
                up2(ev, elo, ehi); up2(en, nlo, nhi);
                e[ci][i] = ev;
                o[ci][i] = pk2(ehi, nlo);
            }
        }

        u64 acc[2] = {0ull, 0ull};
        conv_core(e, o, acc);
        sm.t.st[r0 + 0][jp] = acc[0];
        sm.t.st[r0 + 1][jp] = acc[1];
        __syncthreads();

        const float* stf = (const float*)sm.t.st;
        for (int p = tid; p < 6 * 127; p += 256) {
            const int ly = p / 6, ox_ = p - ly * 6;
            const int oi = oy0 + ly, oj = 2 * TPBASE + ox_;
            const float* rp = stf + ly * 8 + ox_;
            out[(size_t)(b * HO + oi) * WO + oj] =
                (rp[0] + rp[1] + rp[8] + rp[9]) * inv;
        }
    }
}

// ---------------------------------------------------------------------------
// kernel_launch: inputs: x, conv_w, conv_b (cancels under BN), gamma, beta
// ---------------------------------------------------------------------------
extern "C" void kernel_launch(void* const* d_in, const int* in_sizes, int n_in,
                              void* d_out, int out_size) {
    const float* x      = (const float*)d_in[0];
    const float* conv_w = (const float*)d_in[1];
    const float* gamma  = (const float*)d_in[3];
    const float* beta   = (const float*)d_in[4];
    float* out = (float*)d_out;

    void* p_all = 0;
    cudaGetSymbolAddress(&p_all, g_all);

    dim3 sgrid((HF + 2 * SROWS - 1) / (2 * SROWS), BATCH);   // 4 x 64 = 256 blocks
    stats_kernel<<<sgrid, 256>>>(x);
    finalize_kernel<<<1, 128>>>(conv_w, gamma, beta);
    cudaMemcpyToSymbolAsync(c_all, p_all, COUT * CSTR * sizeof(u64),
                            0, cudaMemcpyDeviceToDevice, 0);

    dim3 grid(4, 19, BATCH);   // y<17: main 62x15 tiles; y in {17,18}: thin tile
    fused_out_kernel<<<grid, 256>>>(x, out);
}